// round 2
// baseline (speedup 1.0000x reference)
#include <cuda_runtime.h>
#include <cuda_bf16.h>

// Problem constants (fixed by the dataset)
#define N_NODES 100000
#define N_EDGES 3200000
#define IN_C 5
#define HID_C 128
#define OUT_C 64

// ---------------------------------------------------------------------------
// Scratch (device globals; no allocation allowed)
// ---------------------------------------------------------------------------
__device__ int   g_deg[N_NODES];
__device__ float g_dinv[N_NODES];
__device__ float g_aggx[N_NODES * IN_C];          // aggregated input features
__device__ float g_h[N_NODES * HID_C];            // layer-1 output (51.2 MB)
__device__ float g_t[N_NODES * OUT_C];            // h @ W2 (pre-aggregation, 25.6 MB)

// ---------------------------------------------------------------------------
// K0: zero degree counters
// ---------------------------------------------------------------------------
__global__ void k_zero_deg() {
    int i = blockIdx.x * blockDim.x + threadIdx.x;
    if (i < N_NODES) g_deg[i] = 0;
}

// K1: count in-degree (dst side) with integer atomics (exact, deterministic)
__global__ void k_count_deg(const int* __restrict__ dst) {
    int e = blockIdx.x * blockDim.x + threadIdx.x;
    if (e < N_EDGES) atomicAdd(&g_deg[dst[e]], 1);
}

// K2: deg_inv_sqrt (self-loop adds +1, so deg >= 1 always)
__global__ void k_dinv() {
    int i = blockIdx.x * blockDim.x + threadIdx.x;
    if (i < N_NODES) g_dinv[i] = rsqrtf((float)(g_deg[i] + 1));
}

// ---------------------------------------------------------------------------
// Layer-1 aggregation in the 5-channel INPUT space:  aggx = A_norm @ x
// ---------------------------------------------------------------------------
// K3: init with self-loop term: aggx[n] = x[n] * dinv[n]^2
__global__ void k_aggx_init(const float* __restrict__ x) {
    int n = blockIdx.x * blockDim.x + threadIdx.x;
    if (n >= N_NODES) return;
    float s = g_dinv[n];
    float s2 = s * s;
#pragma unroll
    for (int c = 0; c < IN_C; c++)
        g_aggx[n * IN_C + c] = x[n * IN_C + c] * s2;
}

// K4: edge scatter in input space (5 floats per edge)
__global__ void k_aggx_edges(const float* __restrict__ x,
                             const int* __restrict__ src,
                             const int* __restrict__ dst) {
    int e = blockIdx.x * blockDim.x + threadIdx.x;
    if (e >= N_EDGES) return;
    int s = src[e];
    int d = dst[e];
    float nm = g_dinv[s] * g_dinv[d];
#pragma unroll
    for (int c = 0; c < IN_C; c++)
        atomicAdd(&g_aggx[d * IN_C + c], x[s * IN_C + c] * nm);
}

// ---------------------------------------------------------------------------
// K5: h = aggx @ W1 + b1   (N x 5 @ 5 x 128)
// One block = 2 nodes, 256 threads; thread j computes one output channel.
// ---------------------------------------------------------------------------
__global__ void k_gemm1(const float* __restrict__ W1,
                        const float* __restrict__ b1) {
    int n = blockIdx.x * 2 + (threadIdx.x >> 7);   // node
    int j = threadIdx.x & 127;                     // output channel
    if (n >= N_NODES) return;
    float a0 = g_aggx[n * IN_C + 0];
    float a1 = g_aggx[n * IN_C + 1];
    float a2 = g_aggx[n * IN_C + 2];
    float a3 = g_aggx[n * IN_C + 3];
    float a4 = g_aggx[n * IN_C + 4];
    float acc = b1[j];
    acc += a0 * W1[0 * HID_C + j];
    acc += a1 * W1[1 * HID_C + j];
    acc += a2 * W1[2 * HID_C + j];
    acc += a3 * W1[3 * HID_C + j];
    acc += a4 * W1[4 * HID_C + j];
    g_h[n * HID_C + j] = acc;
}

// ---------------------------------------------------------------------------
// K6: t = h @ W2   (N x 128 @ 128 x 64), no bias (bias added in z-init)
// Block: 256 threads = 4 groups x 64 out-channels; each group handles 8 nodes
// => 32 nodes/block, N % 32 == 0 so no tail guard.
// h rows staged in shared; W2 read through L1 (32 KB, fully cacheable).
// ---------------------------------------------------------------------------
__global__ void k_gemm2(const float* __restrict__ W2) {
    __shared__ float hs[32 * HID_C];               // 16 KB
    int n0 = blockIdx.x * 32;

    // cooperative load of 32 h-rows (4096 floats = 1024 float4)
    const float4* hsrc = (const float4*)(g_h + (size_t)n0 * HID_C);
    float4* hdst = (float4*)hs;
    for (int i = threadIdx.x; i < 32 * HID_C / 4; i += 256)
        hdst[i] = hsrc[i];
    __syncthreads();

    int j = threadIdx.x & 63;                      // out channel
    int gnode = (threadIdx.x >> 6) * 8;            // first node of this group's 8

    float acc[8];
#pragma unroll
    for (int i = 0; i < 8; i++) acc[i] = 0.0f;

#pragma unroll 4
    for (int k = 0; k < HID_C; k++) {
        float w = __ldg(&W2[k * OUT_C + j]);
#pragma unroll
        for (int i = 0; i < 8; i++)
            acc[i] += hs[(gnode + i) * HID_C + k] * w;
    }

#pragma unroll
    for (int i = 0; i < 8; i++)
        g_t[(size_t)(n0 + gnode + i) * OUT_C + j] = acc[i];
}

// ---------------------------------------------------------------------------
// K7: z init with self-loop + bias:  z[n][j] = t[n][j]*dinv[n]^2 + b2[j]
// ---------------------------------------------------------------------------
__global__ void k_z_init(float* __restrict__ z, const float* __restrict__ b2) {
    int idx = blockIdx.x * blockDim.x + threadIdx.x;
    if (idx >= N_NODES * OUT_C) return;
    int n = idx >> 6;      // /64
    int j = idx & 63;
    float s = g_dinv[n];
    z[idx] = g_t[idx] * s * s + b2[j];
}

// ---------------------------------------------------------------------------
// K8: layer-2 edge scatter (64 channels). 16 threads per edge, one float4 each.
// ---------------------------------------------------------------------------
__global__ void k_z_edges(float* __restrict__ z,
                          const int* __restrict__ src,
                          const int* __restrict__ dst) {
    int t = threadIdx.x;
    int e = blockIdx.x * 16 + (t >> 4);
    if (e >= N_EDGES) return;
    int c4 = t & 15;
    int s = src[e];
    int d = dst[e];
    float nm = g_dinv[s] * g_dinv[d];
    float4 v = ((const float4*)g_t)[(size_t)s * 16 + c4];
    float* zp = z + (size_t)d * OUT_C + c4 * 4;
    atomicAdd(zp + 0, v.x * nm);
    atomicAdd(zp + 1, v.y * nm);
    atomicAdd(zp + 2, v.z * nm);
    atomicAdd(zp + 3, v.w * nm);
}

// ---------------------------------------------------------------------------
// Launch
// Inputs (metadata order): x[500000], edge_index[6400000], W1[640], b1[128],
//                          W2[8192], b2[64].   Output: z[6400000] float32.
// ---------------------------------------------------------------------------
extern "C" void kernel_launch(void* const* d_in, const int* in_sizes, int n_in,
                              void* d_out, int out_size) {
    const float* x  = (const float*)d_in[0];
    const int*   ei = (const int*)d_in[1];
    const float* W1 = (const float*)d_in[2];
    const float* b1 = (const float*)d_in[3];
    const float* W2 = (const float*)d_in[4];
    const float* b2 = (const float*)d_in[5];
    float* z = (float*)d_out;

    const int* src = ei;
    const int* dst = ei + N_EDGES;

    // degrees
    k_zero_deg<<<(N_NODES + 255) / 256, 256>>>();
    k_count_deg<<<(N_EDGES + 255) / 256, 256>>>(dst);
    k_dinv<<<(N_NODES + 255) / 256, 256>>>();

    // layer 1: aggregate in input space, then dense 5->128
    k_aggx_init<<<(N_NODES + 255) / 256, 256>>>(x);
    k_aggx_edges<<<(N_EDGES + 255) / 256, 256>>>(x, src, dst);
    k_gemm1<<<(N_NODES + 1) / 2, 256>>>(W1, b1);

    // layer 2: dense 128->64 first, then aggregate in output space
    k_gemm2<<<N_NODES / 32, 256>>>(W2);
    k_z_init<<<(N_NODES * OUT_C + 255) / 256, 256>>>(z, b2);
    k_z_edges<<<(N_EDGES + 15) / 16, 256>>>(z, src, dst);
}

// round 5
// speedup vs baseline: 1.9396x; 1.9396x over previous
#include <cuda_runtime.h>
#include <cuda_bf16.h>

#define N_NODES 100000
#define N_EDGES 3200000
#define IN_C 5
#define OUT_C 64
#define HID_C 128
#define YSTRIDE 8              // 6 used channels padded to 8 floats (32B sector)

// ---------------------------------------------------------------------------
// Scratch (device globals; no allocation allowed)
// ---------------------------------------------------------------------------
__device__ int   g_deg[N_NODES];
__device__ int   g_rowoff[N_NODES + 1];
__device__ int   g_cursor[N_NODES];
__device__ float g_dinv[N_NODES];
__device__ int2  g_adj[N_EDGES];                    // {src, norm bits} per edge, CSR by dst
__device__ float g_y0[N_NODES * YSTRIDE];           // [x | 1]
__device__ float g_y1[N_NODES * YSTRIDE];           // [ÂX | Â1]
__device__ float g_y2[N_NODES * YSTRIDE];           // [Â²X | ...]
__device__ float g_Wc[IN_C * OUT_C];                // W1 @ W2  (5x64)
__device__ float g_bvec[OUT_C];                     // b1 @ W2

// ---------------------------------------------------------------------------
// Degree machinery
// ---------------------------------------------------------------------------
__global__ void k_zero_deg() {
    int i = blockIdx.x * blockDim.x + threadIdx.x;
    if (i < N_NODES) g_deg[i] = 0;
}

__global__ void k_count_deg(const int* __restrict__ dst) {
    int e = blockIdx.x * blockDim.x + threadIdx.x;
    if (e < N_EDGES) atomicAdd(&g_deg[dst[e]], 1);
}

__global__ void k_dinv() {
    int i = blockIdx.x * blockDim.x + threadIdx.x;
    if (i < N_NODES) g_dinv[i] = rsqrtf((float)(g_deg[i] + 1));   // +1 self-loop
}

// Single-block exclusive scan of degrees -> row offsets (+ cursor copy).
__global__ void k_scan() {
    __shared__ int partial[1024];
    const int PER = (N_NODES + 1023) / 1024;        // 98
    int t = threadIdx.x;
    int start = t * PER;
    int sum = 0;
    for (int i = 0; i < PER; i++) {
        int idx = start + i;
        if (idx < N_NODES) sum += g_deg[idx];
    }
    partial[t] = sum;
    __syncthreads();
    // Hillis-Steele inclusive scan
    for (int o = 1; o < 1024; o <<= 1) {
        int v = (t >= o) ? partial[t - o] : 0;
        __syncthreads();
        partial[t] += v;
        __syncthreads();
    }
    int off = (t == 0) ? 0 : partial[t - 1];
    for (int i = 0; i < PER; i++) {
        int idx = start + i;
        if (idx < N_NODES) {
            g_rowoff[idx] = off;
            g_cursor[idx] = off;
            off += g_deg[idx];
        }
    }
    if (t == 1023) g_rowoff[N_NODES] = partial[1023];
}

// Bin edges into CSR-by-dst, precomputing the symmetric norm per edge.
__global__ void k_bin(const int* __restrict__ src, const int* __restrict__ dst) {
    int e = blockIdx.x * blockDim.x + threadIdx.x;
    if (e >= N_EDGES) return;
    int s = src[e];
    int d = dst[e];
    float nm = g_dinv[s] * g_dinv[d];
    int pos = atomicAdd(&g_cursor[d], 1);
    g_adj[pos] = make_int2(s, __float_as_int(nm));
}

// ---------------------------------------------------------------------------
// Pack augmented features: y0[n] = [x[n] (5), 1, 0, 0]
// ---------------------------------------------------------------------------
__global__ void k_pack(const float* __restrict__ x) {
    int n = blockIdx.x * blockDim.x + threadIdx.x;
    if (n >= N_NODES) return;
    const float* xr = x + (size_t)n * IN_C;
    float4 a = make_float4(xr[0], xr[1], xr[2], xr[3]);
    float4 b = make_float4(xr[4], 1.0f, 0.0f, 0.0f);
    float4* yr = (float4*)(g_y0 + (size_t)n * YSTRIDE);
    yr[0] = a;
    yr[1] = b;
}

// Tiny fused weight: Wc = W1 @ W2, bvec = b1 @ W2  (one block, 384 threads)
__global__ void k_wc(const float* __restrict__ W1, const float* __restrict__ b1,
                     const float* __restrict__ W2) {
    int t = threadIdx.x;                 // 0..383
    int c = t >> 6;                      // 0..5
    int j = t & 63;
    float s = 0.0f;
    if (c < IN_C) {
        for (int k = 0; k < HID_C; k++) s += W1[c * HID_C + k] * W2[k * OUT_C + j];
        g_Wc[c * OUT_C + j] = s;
    } else {
        for (int k = 0; k < HID_C; k++) s += b1[k] * W2[k * OUT_C + j];
        g_bvec[j] = s;
    }
}

// ---------------------------------------------------------------------------
// Aggregation: yout = Â @ yin (6 channels). One warp per node.
// PASS selects buffers in DEVICE code — __device__ symbols must not be passed
// as kernel arguments from host (that was the R2 correctness bug).
// ---------------------------------------------------------------------------
template <int PASS>
__global__ void k_agg() {
    const float* __restrict__ yin  = (PASS == 0) ? g_y0 : g_y1;
    float*       __restrict__ yout = (PASS == 0) ? g_y1 : g_y2;

    int warp = (blockIdx.x * blockDim.x + threadIdx.x) >> 5;
    int lane = threadIdx.x & 31;
    if (warp >= N_NODES) return;
    int n  = warp;
    int ro = g_rowoff[n];
    int re = g_rowoff[n + 1];

    float a0 = 0.f, a1 = 0.f, a2 = 0.f, a3 = 0.f, a4 = 0.f, a5 = 0.f;

    for (int base = ro; base < re; base += 32) {
        int k = base + lane;
        int2 e = (k < re) ? __ldg(&g_adj[k]) : make_int2(0, 0);   // nm=0 for pad
        float nm = __int_as_float(e.y);
        const float4* yr = (const float4*)(yin + (size_t)e.x * YSTRIDE);
        float4 v0 = __ldg(yr);
        float4 v1 = __ldg(yr + 1);
        a0 += v0.x * nm;  a1 += v0.y * nm;  a2 += v0.z * nm;
        a3 += v0.w * nm;  a4 += v1.x * nm;  a5 += v1.y * nm;
    }

#pragma unroll
    for (int o = 16; o; o >>= 1) {
        a0 += __shfl_xor_sync(0xffffffffu, a0, o);
        a1 += __shfl_xor_sync(0xffffffffu, a1, o);
        a2 += __shfl_xor_sync(0xffffffffu, a2, o);
        a3 += __shfl_xor_sync(0xffffffffu, a3, o);
        a4 += __shfl_xor_sync(0xffffffffu, a4, o);
        a5 += __shfl_xor_sync(0xffffffffu, a5, o);
    }

    if (lane == 0) {
        float dn = g_dinv[n];
        float self = dn * dn;
        const float4* yr = (const float4*)(yin + (size_t)n * YSTRIDE);
        float4 s0 = __ldg(yr);
        float4 s1 = __ldg(yr + 1);
        float4 o0 = make_float4(a0 + s0.x * self, a1 + s0.y * self,
                                a2 + s0.z * self, a3 + s0.w * self);
        float4 o1 = make_float4(a4 + s1.x * self, a5 + s1.y * self, 0.f, 0.f);
        float4* dst4 = (float4*)(yout + (size_t)n * YSTRIDE);
        dst4[0] = o0;
        dst4[1] = o1;
    }
}

// ---------------------------------------------------------------------------
// Output: z[n][j] = sum_c Y2[n][c]*Wc[c][j] + Y1[n][5]*bvec[j] + b2[j]
// ---------------------------------------------------------------------------
__global__ void k_out(float* __restrict__ z, const float* __restrict__ b2) {
    int idx = blockIdx.x * blockDim.x + threadIdx.x;
    if (idx >= N_NODES * OUT_C) return;
    int n = idx >> 6;
    int j = idx & 63;
    const float* y2 = g_y2 + (size_t)n * YSTRIDE;
    float acc = b2[j] + g_y1[(size_t)n * YSTRIDE + 5] * g_bvec[j];
#pragma unroll
    for (int c = 0; c < IN_C; c++)
        acc += y2[c] * g_Wc[c * OUT_C + j];
    z[idx] = acc;
}

// ---------------------------------------------------------------------------
// Launch. Inputs (metadata order): x, edge_index, W1, b1, W2, b2.
// ---------------------------------------------------------------------------
extern "C" void kernel_launch(void* const* d_in, const int* in_sizes, int n_in,
                              void* d_out, int out_size) {
    const float* x  = (const float*)d_in[0];
    const int*   ei = (const int*)d_in[1];
    const float* W1 = (const float*)d_in[2];
    const float* b1 = (const float*)d_in[3];
    const float* W2 = (const float*)d_in[4];
    const float* b2 = (const float*)d_in[5];
    float* z = (float*)d_out;

    const int* src = ei;
    const int* dst = ei + N_EDGES;

    // CSR build
    k_zero_deg <<<(N_NODES + 255) / 256, 256>>>();
    k_count_deg<<<(N_EDGES + 255) / 256, 256>>>(dst);
    k_dinv     <<<(N_NODES + 255) / 256, 256>>>();
    k_scan     <<<1, 1024>>>();
    k_bin      <<<(N_EDGES + 255) / 256, 256>>>(src, dst);

    // Features + fused weights
    k_pack     <<<(N_NODES + 255) / 256, 256>>>(x);
    k_wc       <<<1, 384>>>(W1, b1, W2);

    // Two 6-channel aggregation passes (warp per node: 8 warps/block)
    k_agg<0>   <<<(N_NODES + 7) / 8, 256>>>();
    k_agg<1>   <<<(N_NODES + 7) / 8, 256>>>();

    // Output projection
    k_out      <<<(N_NODES * OUT_C + 255) / 256, 256>>>(z, b2);
}

// round 6
// speedup vs baseline: 2.7648x; 1.4254x over previous
#include <cuda_runtime.h>
#include <cuda_bf16.h>

#define N_NODES 100000
#define N_EDGES 3200000
#define IN_C 5
#define OUT_C 64
#define HID_C 128
#define YSTRIDE 8              // 6 used channels padded to 8 floats (32B sector)

#define SCAN_BS 512
#define SCAN_NB ((N_NODES + SCAN_BS - 1) / SCAN_BS)   // 196

// ---------------------------------------------------------------------------
// Scratch (device globals; no allocation allowed)
// ---------------------------------------------------------------------------
__device__ int   g_deg[N_NODES];
__device__ int   g_bsum[SCAN_NB];
__device__ int   g_boff[SCAN_NB];
__device__ int   g_rowoff[N_NODES + 1];
__device__ int   g_cursor[N_NODES];
__device__ float g_dinv[N_NODES];
__device__ int2  g_adj[N_EDGES];                    // {src, norm bits} per edge, CSR by dst
__device__ float g_y0[N_NODES * YSTRIDE];           // [x | 1]
__device__ float g_y1[N_NODES * YSTRIDE];           // [ÂX | Â1]
__device__ float g_Wc[IN_C * OUT_C];                // W1 @ W2  (5x64)
__device__ float g_bvec[OUT_C];                     // b1 @ W2

// ---------------------------------------------------------------------------
// Degree machinery
// ---------------------------------------------------------------------------
__global__ void k_zero_deg() {
    int i = blockIdx.x * blockDim.x + threadIdx.x;
    if (i < N_NODES) g_deg[i] = 0;
}

__global__ void k_count_deg(const int* __restrict__ dst) {
    int e = blockIdx.x * blockDim.x + threadIdx.x;
    if (e < N_EDGES) atomicAdd(&g_deg[dst[e]], 1);
}

// ---- Phase A: per-block degree sums (coalesced, full chip) ----
__global__ void k_bsum() {
    __shared__ int wsum[SCAN_BS / 32];
    int t = threadIdx.x;
    int i = blockIdx.x * SCAN_BS + t;
    int v = (i < N_NODES) ? g_deg[i] : 0;
#pragma unroll
    for (int o = 16; o; o >>= 1) v += __shfl_xor_sync(0xffffffffu, v, o);
    if ((t & 31) == 0) wsum[t >> 5] = v;
    __syncthreads();
    if (t < 32) {
        int w = (t < SCAN_BS / 32) ? wsum[t] : 0;
#pragma unroll
        for (int o = 16; o; o >>= 1) w += __shfl_xor_sync(0xffffffffu, w, o);
        if (t == 0) g_bsum[blockIdx.x] = w;
    }
}

// ---- Phase B: scan the 196 block sums (single tiny block) ----
__global__ void k_scan_small() {
    __shared__ int s[256];
    int t = threadIdx.x;
    int v = (t < SCAN_NB) ? g_bsum[t] : 0;
    s[t] = v;
    __syncthreads();
    for (int o = 1; o < 256; o <<= 1) {
        int u = (t >= o) ? s[t - o] : 0;
        __syncthreads();
        s[t] += u;
        __syncthreads();
    }
    if (t < SCAN_NB) g_boff[t] = s[t] - v;          // exclusive
    if (t == 0) g_rowoff[N_NODES] = N_EDGES;        // all dsts are valid nodes
}

// ---- Phase C: intra-block exclusive scan + block offset; also dinv ----
__global__ void k_rowoff() {
    __shared__ int wsum[SCAN_BS / 32];
    int t = threadIdx.x;
    int lane = t & 31, wid = t >> 5;
    int i = blockIdx.x * SCAN_BS + t;
    int v = (i < N_NODES) ? g_deg[i] : 0;

    int incl = v;
#pragma unroll
    for (int o = 1; o < 32; o <<= 1) {
        int u = __shfl_up_sync(0xffffffffu, incl, o);
        if (lane >= o) incl += u;
    }
    if (lane == 31) wsum[wid] = incl;
    __syncthreads();
    if (wid == 0) {
        int w = (lane < SCAN_BS / 32) ? wsum[lane] : 0;
#pragma unroll
        for (int o = 1; o < SCAN_BS / 32; o <<= 1) {
            int u = __shfl_up_sync(0xffffffffu, w, o);
            if (lane >= o) w += u;
        }
        if (lane < SCAN_BS / 32) wsum[lane] = w;
    }
    __syncthreads();

    if (i < N_NODES) {
        int off = g_boff[blockIdx.x] + (incl - v) + (wid ? wsum[wid - 1] : 0);
        g_rowoff[i] = off;
        g_cursor[i] = off;
        g_dinv[i]   = rsqrtf((float)(v + 1));       // +1 self-loop
    }
}

// Bin edges into CSR-by-dst, precomputing the symmetric norm per edge.
__global__ void k_bin(const int* __restrict__ src, const int* __restrict__ dst) {
    int e = blockIdx.x * blockDim.x + threadIdx.x;
    if (e >= N_EDGES) return;
    int s = src[e];
    int d = dst[e];
    float nm = g_dinv[s] * g_dinv[d];
    int pos = atomicAdd(&g_cursor[d], 1);
    g_adj[pos] = make_int2(s, __float_as_int(nm));
}

// ---------------------------------------------------------------------------
// Pack augmented features: y0[n] = [x[n] (5), 1, 0, 0]
// ---------------------------------------------------------------------------
__global__ void k_pack(const float* __restrict__ x) {
    int n = blockIdx.x * blockDim.x + threadIdx.x;
    if (n >= N_NODES) return;
    const float* xr = x + (size_t)n * IN_C;
    float4 a = make_float4(xr[0], xr[1], xr[2], xr[3]);
    float4 b = make_float4(xr[4], 1.0f, 0.0f, 0.0f);
    float4* yr = (float4*)(g_y0 + (size_t)n * YSTRIDE);
    yr[0] = a;
    yr[1] = b;
}

// Tiny fused weight: Wc = W1 @ W2, bvec = b1 @ W2  (one block, 384 threads)
__global__ void k_wc(const float* __restrict__ W1, const float* __restrict__ b1,
                     const float* __restrict__ W2) {
    int t = threadIdx.x;                 // 0..383
    int c = t >> 6;                      // 0..5
    int j = t & 63;
    float s = 0.0f;
    if (c < IN_C) {
        for (int k = 0; k < HID_C; k++) s += W1[c * HID_C + k] * W2[k * OUT_C + j];
        g_Wc[c * OUT_C + j] = s;
    } else {
        for (int k = 0; k < HID_C; k++) s += b1[k] * W2[k * OUT_C + j];
        g_bvec[j] = s;
    }
}

// ---------------------------------------------------------------------------
// Aggregation: one warp per node. PASS 0: y1 = Â y0 (written to g_y1).
// PASS 1: fused epilogue — each lane computes 2 of the 64 output channels
// directly (xor-reduction leaves full sums in ALL lanes; self-term added
// per-lane from a broadcast load).
// ---------------------------------------------------------------------------
template <int PASS>
__global__ void k_agg(float* __restrict__ z, const float* __restrict__ b2) {
    const float* __restrict__ yin = (PASS == 0) ? g_y0 : g_y1;

    int warp = (blockIdx.x * blockDim.x + threadIdx.x) >> 5;
    int lane = threadIdx.x & 31;
    if (warp >= N_NODES) return;
    int n  = warp;
    int ro = g_rowoff[n];
    int re = g_rowoff[n + 1];

    float a0 = 0.f, a1 = 0.f, a2 = 0.f, a3 = 0.f, a4 = 0.f, a5 = 0.f;

    for (int base = ro; base < re; base += 32) {
        int k = base + lane;
        int2 e = (k < re) ? __ldg(&g_adj[k]) : make_int2(0, 0);   // nm=0 for pad
        float nm = __int_as_float(e.y);
        const float4* yr = (const float4*)(yin + (size_t)e.x * YSTRIDE);
        float4 v0 = __ldg(yr);
        float4 v1 = __ldg(yr + 1);
        a0 += v0.x * nm;  a1 += v0.y * nm;  a2 += v0.z * nm;
        a3 += v0.w * nm;  a4 += v1.x * nm;  a5 += v1.y * nm;
    }

#pragma unroll
    for (int o = 16; o; o >>= 1) {
        a0 += __shfl_xor_sync(0xffffffffu, a0, o);
        a1 += __shfl_xor_sync(0xffffffffu, a1, o);
        a2 += __shfl_xor_sync(0xffffffffu, a2, o);
        a3 += __shfl_xor_sync(0xffffffffu, a3, o);
        a4 += __shfl_xor_sync(0xffffffffu, a4, o);
        a5 += __shfl_xor_sync(0xffffffffu, a5, o);
    }

    // self-loop term (broadcast load: all lanes, same address)
    float dn = g_dinv[n];
    float self = dn * dn;
    const float4* yr = (const float4*)(yin + (size_t)n * YSTRIDE);
    float4 s0 = __ldg(yr);
    float4 s1 = __ldg(yr + 1);
    float o0 = a0 + s0.x * self;
    float o1 = a1 + s0.y * self;
    float o2 = a2 + s0.z * self;
    float o3 = a3 + s0.w * self;
    float o4 = a4 + s1.x * self;
    float o5 = a5 + s1.y * self;

    if (PASS == 0) {
        if (lane == 0) {
            float4* dst4 = (float4*)(g_y1 + (size_t)n * YSTRIDE);
            dst4[0] = make_float4(o0, o1, o2, o3);
            dst4[1] = make_float4(o4, o5, 0.f, 0.f);
        }
    } else {
        // z[n][j] = sum_c o_c * Wc[c][j] + y1[n][5]*bvec[j] + b2[j]
        float y15 = s1.y;                 // self row of y1, channel 5
        float* zr = z + (size_t)n * OUT_C;
#pragma unroll
        for (int h = 0; h < 2; h++) {
            int j = lane + h * 32;
            float acc = __ldg(&b2[j]) + y15 * g_bvec[j];
            acc += o0 * g_Wc[0 * OUT_C + j];
            acc += o1 * g_Wc[1 * OUT_C + j];
            acc += o2 * g_Wc[2 * OUT_C + j];
            acc += o3 * g_Wc[3 * OUT_C + j];
            acc += o4 * g_Wc[4 * OUT_C + j];
            zr[j] = acc;
        }
    }
}

// ---------------------------------------------------------------------------
// Launch. Inputs (metadata order): x, edge_index, W1, b1, W2, b2.
// ---------------------------------------------------------------------------
extern "C" void kernel_launch(void* const* d_in, const int* in_sizes, int n_in,
                              void* d_out, int out_size) {
    const float* x  = (const float*)d_in[0];
    const int*   ei = (const int*)d_in[1];
    const float* W1 = (const float*)d_in[2];
    const float* b1 = (const float*)d_in[3];
    const float* W2 = (const float*)d_in[4];
    const float* b2 = (const float*)d_in[5];
    float* z = (float*)d_out;

    const int* src = ei;
    const int* dst = ei + N_EDGES;

    // CSR build (chip-wide 3-phase scan)
    k_zero_deg  <<<(N_NODES + 255) / 256, 256>>>();
    k_count_deg <<<(N_EDGES + 255) / 256, 256>>>(dst);
    k_bsum      <<<SCAN_NB, SCAN_BS>>>();
    k_scan_small<<<1, 256>>>();
    k_rowoff    <<<SCAN_NB, SCAN_BS>>>();
    k_bin       <<<(N_EDGES + 255) / 256, 256>>>(src, dst);

    // Features + fused weights
    k_pack      <<<(N_NODES + 255) / 256, 256>>>(x);
    k_wc        <<<1, 384>>>(W1, b1, W2);

    // Two aggregation passes (warp per node); pass 2 fuses output projection
    k_agg<0>    <<<(N_NODES + 7) / 8, 256>>>(z, b2);
    k_agg<1>    <<<(N_NODES + 7) / 8, 256>>>(z, b2);
}

// round 7
// speedup vs baseline: 3.1916x; 1.1544x over previous
#include <cuda_runtime.h>
#include <cuda_bf16.h>

#define N_NODES 100000
#define N_EDGES 3200000
#define IN_C 5
#define OUT_C 64
#define HID_C 128
#define YSTRIDE 8              // 6 used channels + spare, 32B row = 1 sector

#define SCAN_BS 512
#define SCAN_NB ((N_NODES + SCAN_BS - 1) / SCAN_BS)   // 196

// ---------------------------------------------------------------------------
// Scratch (device globals; no allocation allowed)
// ---------------------------------------------------------------------------
__device__ int   g_deg[N_NODES];
__device__ int   g_bsum[SCAN_NB];
__device__ int   g_boff[SCAN_NB];
__device__ int   g_rowoff[N_NODES + 1];
__device__ int   g_cursor[N_NODES];
__device__ float g_dinv[N_NODES];
__device__ int   g_adj[N_EDGES];                      // src only, CSR by dst
__device__ float g_ys0[(N_NODES + 1) * YSTRIDE];      // dinv*[x | 1]; row N = 0
__device__ float g_ys1[(N_NODES + 1) * YSTRIDE];      // dinv*out1 (+ ch6 = Â1)
__device__ float g_Wc[IN_C * OUT_C];                  // W1 @ W2  (5x64)
__device__ float g_bvec[OUT_C];                       // b1 @ W2

// ---------------------------------------------------------------------------
// Degree machinery
// ---------------------------------------------------------------------------
__global__ void k_zero_deg() {
    int i = blockIdx.x * blockDim.x + threadIdx.x;
    if (i < N_NODES) g_deg[i] = 0;
}

// 4 edges per thread (N_EDGES % 4 == 0)
__global__ void k_count_deg(const int4* __restrict__ dst4) {
    int i = blockIdx.x * blockDim.x + threadIdx.x;
    if (i >= N_EDGES / 4) return;
    int4 d = __ldg(&dst4[i]);
    atomicAdd(&g_deg[d.x], 1);
    atomicAdd(&g_deg[d.y], 1);
    atomicAdd(&g_deg[d.z], 1);
    atomicAdd(&g_deg[d.w], 1);
}

// ---- Phase A: per-block degree sums ----
__global__ void k_bsum() {
    __shared__ int wsum[SCAN_BS / 32];
    int t = threadIdx.x;
    int i = blockIdx.x * SCAN_BS + t;
    int v = (i < N_NODES) ? g_deg[i] : 0;
#pragma unroll
    for (int o = 16; o; o >>= 1) v += __shfl_xor_sync(0xffffffffu, v, o);
    if ((t & 31) == 0) wsum[t >> 5] = v;
    __syncthreads();
    if (t < 32) {
        int w = (t < SCAN_BS / 32) ? wsum[t] : 0;
#pragma unroll
        for (int o = 16; o; o >>= 1) w += __shfl_xor_sync(0xffffffffu, w, o);
        if (t == 0) g_bsum[blockIdx.x] = w;
    }
}

// ---- Phase B: scan 196 block sums (one tiny block) ----
__global__ void k_scan_small() {
    __shared__ int s[256];
    int t = threadIdx.x;
    int v = (t < SCAN_NB) ? g_bsum[t] : 0;
    s[t] = v;
    __syncthreads();
    for (int o = 1; o < 256; o <<= 1) {
        int u = (t >= o) ? s[t - o] : 0;
        __syncthreads();
        s[t] += u;
        __syncthreads();
    }
    if (t < SCAN_NB) g_boff[t] = s[t] - v;          // exclusive
    if (t == 0) g_rowoff[N_NODES] = N_EDGES;
}

// ---- Phase C: intra-block exclusive scan + dinv ----
__global__ void k_rowoff() {
    __shared__ int wsum[SCAN_BS / 32];
    int t = threadIdx.x;
    int lane = t & 31, wid = t >> 5;
    int i = blockIdx.x * SCAN_BS + t;
    int v = (i < N_NODES) ? g_deg[i] : 0;

    int incl = v;
#pragma unroll
    for (int o = 1; o < 32; o <<= 1) {
        int u = __shfl_up_sync(0xffffffffu, incl, o);
        if (lane >= o) incl += u;
    }
    if (lane == 31) wsum[wid] = incl;
    __syncthreads();
    if (wid == 0) {
        int w = (lane < SCAN_BS / 32) ? wsum[lane] : 0;
#pragma unroll
        for (int o = 1; o < SCAN_BS / 32; o <<= 1) {
            int u = __shfl_up_sync(0xffffffffu, w, o);
            if (lane >= o) w += u;
        }
        if (lane < SCAN_BS / 32) wsum[lane] = w;
    }
    __syncthreads();

    if (i < N_NODES) {
        int off = g_boff[blockIdx.x] + (incl - v) + (wid ? wsum[wid - 1] : 0);
        g_rowoff[i] = off;
        g_cursor[i] = off;
        g_dinv[i]   = rsqrtf((float)(v + 1));       // +1 self-loop
    }
}

// Bin edges into CSR-by-dst: src index only (norm folded into features).
__global__ void k_bin(const int4* __restrict__ src4, const int4* __restrict__ dst4) {
    int i = blockIdx.x * blockDim.x + threadIdx.x;
    if (i >= N_EDGES / 4) return;
    int4 s = __ldg(&src4[i]);
    int4 d = __ldg(&dst4[i]);
    g_adj[atomicAdd(&g_cursor[d.x], 1)] = s.x;
    g_adj[atomicAdd(&g_cursor[d.y], 1)] = s.y;
    g_adj[atomicAdd(&g_cursor[d.z], 1)] = s.z;
    g_adj[atomicAdd(&g_cursor[d.w], 1)] = s.w;
}

// ---------------------------------------------------------------------------
// Pack pre-scaled features: ys0[n] = dinv[n]*[x(5), 1], pad row N = 0
// (Also zeroes pad row of ys1 so pass-1 pad gathers read zeros.)
// ---------------------------------------------------------------------------
__global__ void k_pack(const float* __restrict__ x) {
    int n = blockIdx.x * blockDim.x + threadIdx.x;
    if (n > N_NODES) return;
    float4* yr = (float4*)(g_ys0 + (size_t)n * YSTRIDE);
    if (n == N_NODES) {
        float4 zz = make_float4(0.f, 0.f, 0.f, 0.f);
        yr[0] = zz; yr[1] = zz;
        float4* y1r = (float4*)(g_ys1 + (size_t)n * YSTRIDE);
        y1r[0] = zz; y1r[1] = zz;
        return;
    }
    float dn = g_dinv[n];
    const float* xr = x + (size_t)n * IN_C;
    yr[0] = make_float4(dn * xr[0], dn * xr[1], dn * xr[2], dn * xr[3]);
    yr[1] = make_float4(dn * xr[4], dn, 0.f, 0.f);
}

// Fused weights: Wc = W1 @ W2, bvec = b1 @ W2  (one block, 384 threads)
__global__ void k_wc(const float* __restrict__ W1, const float* __restrict__ b1,
                     const float* __restrict__ W2) {
    int t = threadIdx.x;
    int c = t >> 6;                      // 0..5
    int j = t & 63;
    float s = 0.0f;
    if (c < IN_C) {
        for (int k = 0; k < HID_C; k++) s += W1[c * HID_C + k] * W2[k * OUT_C + j];
        g_Wc[c * OUT_C + j] = s;
    } else {
        for (int k = 0; k < HID_C; k++) s += b1[k] * W2[k * OUT_C + j];
        g_bvec[j] = s;
    }
}

// ---------------------------------------------------------------------------
// Aggregation, warp per node, norm-free inner loop (pure adds).
// PASS 0: ys1[n][c] = dinv²(Σ ys0 + ys0[n]) for c=0..5; ch6 = (Â1)[n].
// PASS 1: out2_c = dinv(Σ ys1 + ys1[n]) for c=0..4; fused output projection.
// ---------------------------------------------------------------------------
template <int PASS>
__global__ void k_agg(float* __restrict__ z, const float* __restrict__ b2) {
    const float* __restrict__ yin = (PASS == 0) ? g_ys0 : g_ys1;

    int warp = (blockIdx.x * blockDim.x + threadIdx.x) >> 5;
    int lane = threadIdx.x & 31;
    if (warp >= N_NODES) return;
    int n  = warp;
    int ro = g_rowoff[n];
    int re = g_rowoff[n + 1];

    float a0 = 0.f, a1 = 0.f, a2 = 0.f, a3 = 0.f, a4 = 0.f, a5 = 0.f;

    for (int base = ro; base < re; base += 32) {
        int k = base + lane;
        int s = (k < re) ? __ldg(&g_adj[k]) : N_NODES;   // pad row = zeros
        const float4* yr = (const float4*)(yin + (size_t)s * YSTRIDE);
        float4 v0 = __ldg(yr);
        float4 v1 = __ldg(yr + 1);
        a0 += v0.x;  a1 += v0.y;  a2 += v0.z;  a3 += v0.w;  a4 += v1.x;
        if (PASS == 0) a5 += v1.y;
    }

#pragma unroll
    for (int o = 16; o; o >>= 1) {
        a0 += __shfl_xor_sync(0xffffffffu, a0, o);
        a1 += __shfl_xor_sync(0xffffffffu, a1, o);
        a2 += __shfl_xor_sync(0xffffffffu, a2, o);
        a3 += __shfl_xor_sync(0xffffffffu, a3, o);
        a4 += __shfl_xor_sync(0xffffffffu, a4, o);
        if (PASS == 0) a5 += __shfl_xor_sync(0xffffffffu, a5, o);
    }

    float dn = g_dinv[n];
    const float4* yr = (const float4*)(yin + (size_t)n * YSTRIDE);
    float4 s0 = __ldg(yr);                // self row (broadcast)
    float4 s1 = __ldg(yr + 1);

    if (PASS == 0) {
        float o0 = dn * (a0 + s0.x);
        float o1 = dn * (a1 + s0.y);
        float o2 = dn * (a2 + s0.z);
        float o3 = dn * (a3 + s0.w);
        float o4 = dn * (a4 + s1.x);
        float o5 = dn * (a5 + s1.y);      // (Â1)[n], unscaled
        if (lane == 0) {
            float4* d4 = (float4*)(g_ys1 + (size_t)n * YSTRIDE);
            d4[0] = make_float4(dn * o0, dn * o1, dn * o2, dn * o3);
            d4[1] = make_float4(dn * o4, dn * o5, o5, 0.f);
        }
    } else {
        float o0 = dn * (a0 + s0.x);
        float o1 = dn * (a1 + s0.y);
        float o2 = dn * (a2 + s0.z);
        float o3 = dn * (a3 + s0.w);
        float o4 = dn * (a4 + s1.x);
        float ab1 = s1.z;                 // (Â1)[n] stashed in channel 6
        float* zr = z + (size_t)n * OUT_C;
#pragma unroll
        for (int h = 0; h < 2; h++) {
            int j = lane + h * 32;
            float acc = __ldg(&b2[j]) + ab1 * g_bvec[j];
            acc += o0 * g_Wc[0 * OUT_C + j];
            acc += o1 * g_Wc[1 * OUT_C + j];
            acc += o2 * g_Wc[2 * OUT_C + j];
            acc += o3 * g_Wc[3 * OUT_C + j];
            acc += o4 * g_Wc[4 * OUT_C + j];
            zr[j] = acc;
        }
    }
}

// ---------------------------------------------------------------------------
// Launch. Inputs (metadata order): x, edge_index, W1, b1, W2, b2.
// ---------------------------------------------------------------------------
extern "C" void kernel_launch(void* const* d_in, const int* in_sizes, int n_in,
                              void* d_out, int out_size) {
    const float* x  = (const float*)d_in[0];
    const int*   ei = (const int*)d_in[1];
    const float* W1 = (const float*)d_in[2];
    const float* b1 = (const float*)d_in[3];
    const float* W2 = (const float*)d_in[4];
    const float* b2 = (const float*)d_in[5];
    float* z = (float*)d_out;

    const int4* src4 = (const int4*)ei;
    const int4* dst4 = (const int4*)(ei + N_EDGES);

    // CSR build
    k_zero_deg  <<<(N_NODES + 255) / 256, 256>>>();
    k_count_deg <<<(N_EDGES / 4 + 255) / 256, 256>>>(dst4);
    k_bsum      <<<SCAN_NB, SCAN_BS>>>();
    k_scan_small<<<1, 256>>>();
    k_rowoff    <<<SCAN_NB, SCAN_BS>>>();
    k_bin       <<<(N_EDGES / 4 + 255) / 256, 256>>>(src4, dst4);

    // Pre-scaled features + fused weights
    k_pack      <<<(N_NODES + 256) / 256, 256>>>(x);
    k_wc        <<<1, 384>>>(W1, b1, W2);

    // Two aggregation passes (warp per node); pass 2 fuses output projection
    k_agg<0>    <<<(N_NODES + 7) / 8, 256>>>(z, b2);
    k_agg<1>    <<<(N_NODES + 7) / 8, 256>>>(z, b2);
}

// round 8
// speedup vs baseline: 4.3087x; 1.3500x over previous
#include <cuda_runtime.h>
#include <cuda_bf16.h>

#define N_NODES 100000
#define N_EDGES 3200000
#define IN_C 5
#define OUT_C 64
#define HID_C 128
#define YSTRIDE 8              // 6 used channels + spare, 32B row = 1 sector

#define SCAN_BS 512
#define SCAN_NB ((N_NODES + SCAN_BS - 1) / SCAN_BS)   // 196

// ---------------------------------------------------------------------------
// Scratch (device globals; no allocation allowed)
// ---------------------------------------------------------------------------
__device__ int   g_deg[N_NODES];
__device__ int   g_bsum[SCAN_NB];
__device__ int   g_rowoff[N_NODES + 1];
__device__ int   g_cursor[N_NODES];
__device__ float g_dinv[N_NODES];
__device__ int   g_adj[N_EDGES];                      // src only, CSR by dst
__device__ float g_ys0[(N_NODES + 1) * YSTRIDE];      // dinv*[x | 1]; row N = 0
__device__ float g_ys1[(N_NODES + 1) * YSTRIDE];      // dinv*out1 (+ ch6 = Â1)
__device__ float g_Wc[IN_C * OUT_C];                  // W1 @ W2  (5x64)
__device__ float g_bvec[OUT_C];                       // b1 @ W2

// ---------------------------------------------------------------------------
// K1: zero degree counters
// ---------------------------------------------------------------------------
__global__ void k_zero_deg() {
    int i = blockIdx.x * blockDim.x + threadIdx.x;
    if (i < N_NODES) g_deg[i] = 0;
}

// K2: count in-degree, 8 edges/thread (N_EDGES % 8 == 0), no-return atomics
__global__ void k_count_deg(const int4* __restrict__ dst4) {
    int i = blockIdx.x * blockDim.x + threadIdx.x;
    if (i >= N_EDGES / 8) return;
    int4 d0 = __ldg(&dst4[2 * i]);
    int4 d1 = __ldg(&dst4[2 * i + 1]);
    atomicAdd(&g_deg[d0.x], 1);
    atomicAdd(&g_deg[d0.y], 1);
    atomicAdd(&g_deg[d0.z], 1);
    atomicAdd(&g_deg[d0.w], 1);
    atomicAdd(&g_deg[d1.x], 1);
    atomicAdd(&g_deg[d1.y], 1);
    atomicAdd(&g_deg[d1.z], 1);
    atomicAdd(&g_deg[d1.w], 1);
}

// K3: per-block degree sums
__global__ void k_bsum() {
    __shared__ int wsum[SCAN_BS / 32];
    int t = threadIdx.x;
    int i = blockIdx.x * SCAN_BS + t;
    int v = (i < N_NODES) ? g_deg[i] : 0;
#pragma unroll
    for (int o = 16; o; o >>= 1) v += __shfl_xor_sync(0xffffffffu, v, o);
    if ((t & 31) == 0) wsum[t >> 5] = v;
    __syncthreads();
    if (t < 32) {
        int w = (t < SCAN_BS / 32) ? wsum[t] : 0;
#pragma unroll
        for (int o = 16; o; o >>= 1) w += __shfl_xor_sync(0xffffffffu, w, o);
        if (t == 0) g_bsum[blockIdx.x] = w;
    }
}

// ---------------------------------------------------------------------------
// K4 (fused): blocks 0..SCAN_NB-1 — redundant in-block scan of the 196 block
// sums, local exclusive scan, rowoff/cursor/dinv, and ys0 pack.
// Block SCAN_NB — fused weights Wc/bvec, pad-row zeroing, rowoff[N].
// ---------------------------------------------------------------------------
__global__ void k_fuse(const float* __restrict__ x,
                       const float* __restrict__ W1,
                       const float* __restrict__ b1,
                       const float* __restrict__ W2) {
    int t = threadIdx.x;

    if (blockIdx.x == SCAN_NB) {
        // --- weight collapse + housekeeping ---
        if (t < 384) {
            int c = t >> 6;                  // 0..5
            int j = t & 63;
            float s = 0.0f;
            if (c < IN_C) {
                for (int k = 0; k < HID_C; k++)
                    s += W1[c * HID_C + k] * W2[k * OUT_C + j];
                g_Wc[c * OUT_C + j] = s;
            } else {
                for (int k = 0; k < HID_C; k++)
                    s += b1[k] * W2[k * OUT_C + j];
                g_bvec[j] = s;
            }
        } else if (t < 384 + 16) {
            // zero pad rows (row N_NODES) of ys0 and ys1
            int q = t - 384;                 // 0..15
            if (q < 8)      g_ys0[(size_t)N_NODES * YSTRIDE + q] = 0.f;
            else            g_ys1[(size_t)N_NODES * YSTRIDE + (q - 8)] = 0.f;
        } else if (t == 400) {
            g_rowoff[N_NODES] = N_EDGES;
        }
        return;
    }

    // --- scan the 196 block sums (redundant per block; cheap) ---
    __shared__ int s196[256];
    __shared__ int wsum[SCAN_BS / 32];
    if (t < 256) s196[t] = (t < SCAN_NB) ? g_bsum[t] : 0;
    __syncthreads();
    for (int o = 1; o < 256; o <<= 1) {
        int u = 0;
        if (t < 256 && t >= o) u = s196[t - o];
        __syncthreads();
        if (t < 256) s196[t] += u;
        __syncthreads();
    }
    int boff = (blockIdx.x == 0) ? 0 : s196[blockIdx.x - 1];

    // --- local exclusive scan over this block's 512 degrees ---
    int lane = t & 31, wid = t >> 5;
    int i = blockIdx.x * SCAN_BS + t;
    int v = (i < N_NODES) ? g_deg[i] : 0;

    int incl = v;
#pragma unroll
    for (int o = 1; o < 32; o <<= 1) {
        int u = __shfl_up_sync(0xffffffffu, incl, o);
        if (lane >= o) incl += u;
    }
    if (lane == 31) wsum[wid] = incl;
    __syncthreads();
    if (wid == 0) {
        int w = (lane < SCAN_BS / 32) ? wsum[lane] : 0;
#pragma unroll
        for (int o = 1; o < SCAN_BS / 32; o <<= 1) {
            int u = __shfl_up_sync(0xffffffffu, w, o);
            if (lane >= o) w += u;
        }
        if (lane < SCAN_BS / 32) wsum[lane] = w;
    }
    __syncthreads();

    if (i < N_NODES) {
        int off = boff + (incl - v) + (wid ? wsum[wid - 1] : 0);
        g_rowoff[i] = off;
        g_cursor[i] = off;
        float dn = rsqrtf((float)(v + 1));   // +1 self-loop
        g_dinv[i] = dn;
        // pack pre-scaled features
        const float* xr = x + (size_t)i * IN_C;
        float4* yr = (float4*)(g_ys0 + (size_t)i * YSTRIDE);
        yr[0] = make_float4(dn * xr[0], dn * xr[1], dn * xr[2], dn * xr[3]);
        yr[1] = make_float4(dn * xr[4], dn, 0.f, 0.f);
    }
}

// ---------------------------------------------------------------------------
// K5: bin edges into CSR-by-dst (src only). 8 edges/thread for ATOMG MLP.
// ---------------------------------------------------------------------------
__global__ void k_bin(const int4* __restrict__ src4, const int4* __restrict__ dst4) {
    int i = blockIdx.x * blockDim.x + threadIdx.x;
    if (i >= N_EDGES / 8) return;
    int4 s0 = __ldg(&src4[2 * i]);
    int4 s1 = __ldg(&src4[2 * i + 1]);
    int4 d0 = __ldg(&dst4[2 * i]);
    int4 d1 = __ldg(&dst4[2 * i + 1]);
    int p0 = atomicAdd(&g_cursor[d0.x], 1);
    int p1 = atomicAdd(&g_cursor[d0.y], 1);
    int p2 = atomicAdd(&g_cursor[d0.z], 1);
    int p3 = atomicAdd(&g_cursor[d0.w], 1);
    int p4 = atomicAdd(&g_cursor[d1.x], 1);
    int p5 = atomicAdd(&g_cursor[d1.y], 1);
    int p6 = atomicAdd(&g_cursor[d1.z], 1);
    int p7 = atomicAdd(&g_cursor[d1.w], 1);
    g_adj[p0] = s0.x;
    g_adj[p1] = s0.y;
    g_adj[p2] = s0.z;
    g_adj[p3] = s0.w;
    g_adj[p4] = s1.x;
    g_adj[p5] = s1.y;
    g_adj[p6] = s1.z;
    g_adj[p7] = s1.w;
}

// ---------------------------------------------------------------------------
// Aggregation, warp per node, norm-free inner loop (pure adds).
// PASS 0: ys1[n][c] = dinv²(Σ ys0 + ys0[n]) for c=0..5; ch6 = (Â1)[n].
// PASS 1: out2_c = dinv(Σ ys1 + ys1[n]) for c=0..4; fused output projection.
// ---------------------------------------------------------------------------
template <int PASS>
__global__ void k_agg(float* __restrict__ z, const float* __restrict__ b2) {
    const float* __restrict__ yin = (PASS == 0) ? g_ys0 : g_ys1;

    int warp = (blockIdx.x * blockDim.x + threadIdx.x) >> 5;
    int lane = threadIdx.x & 31;
    if (warp >= N_NODES) return;
    int n  = warp;
    int ro = g_rowoff[n];
    int re = g_rowoff[n + 1];

    float a0 = 0.f, a1 = 0.f, a2 = 0.f, a3 = 0.f, a4 = 0.f, a5 = 0.f;

    for (int base = ro; base < re; base += 32) {
        int k = base + lane;
        int s = (k < re) ? __ldg(&g_adj[k]) : N_NODES;   // pad row = zeros
        const float4* yr = (const float4*)(yin + (size_t)s * YSTRIDE);
        float4 v0 = __ldg(yr);
        float4 v1 = __ldg(yr + 1);
        a0 += v0.x;  a1 += v0.y;  a2 += v0.z;  a3 += v0.w;  a4 += v1.x;
        if (PASS == 0) a5 += v1.y;
    }

#pragma unroll
    for (int o = 16; o; o >>= 1) {
        a0 += __shfl_xor_sync(0xffffffffu, a0, o);
        a1 += __shfl_xor_sync(0xffffffffu, a1, o);
        a2 += __shfl_xor_sync(0xffffffffu, a2, o);
        a3 += __shfl_xor_sync(0xffffffffu, a3, o);
        a4 += __shfl_xor_sync(0xffffffffu, a4, o);
        if (PASS == 0) a5 += __shfl_xor_sync(0xffffffffu, a5, o);
    }

    float dn = g_dinv[n];
    const float4* yr = (const float4*)(yin + (size_t)n * YSTRIDE);
    float4 s0 = __ldg(yr);                // self row (broadcast)
    float4 s1 = __ldg(yr + 1);

    if (PASS == 0) {
        float o0 = dn * (a0 + s0.x);
        float o1 = dn * (a1 + s0.y);
        float o2 = dn * (a2 + s0.z);
        float o3 = dn * (a3 + s0.w);
        float o4 = dn * (a4 + s1.x);
        float o5 = dn * (a5 + s1.y);      // (Â1)[n], unscaled
        if (lane == 0) {
            float4* d4 = (float4*)(g_ys1 + (size_t)n * YSTRIDE);
            d4[0] = make_float4(dn * o0, dn * o1, dn * o2, dn * o3);
            d4[1] = make_float4(dn * o4, dn * o5, o5, 0.f);
        }
    } else {
        float o0 = dn * (a0 + s0.x);
        float o1 = dn * (a1 + s0.y);
        float o2 = dn * (a2 + s0.z);
        float o3 = dn * (a3 + s0.w);
        float o4 = dn * (a4 + s1.x);
        float ab1 = s1.z;                 // (Â1)[n] stashed in channel 6
        float* zr = z + (size_t)n * OUT_C;
#pragma unroll
        for (int h = 0; h < 2; h++) {
            int j = lane + h * 32;
            float acc = __ldg(&b2[j]) + ab1 * g_bvec[j];
            acc += o0 * g_Wc[0 * OUT_C + j];
            acc += o1 * g_Wc[1 * OUT_C + j];
            acc += o2 * g_Wc[2 * OUT_C + j];
            acc += o3 * g_Wc[3 * OUT_C + j];
            acc += o4 * g_Wc[4 * OUT_C + j];
            zr[j] = acc;
        }
    }
}

// ---------------------------------------------------------------------------
// Launch. Inputs (metadata order): x, edge_index, W1, b1, W2, b2.
// ---------------------------------------------------------------------------
extern "C" void kernel_launch(void* const* d_in, const int* in_sizes, int n_in,
                              void* d_out, int out_size) {
    const float* x  = (const float*)d_in[0];
    const int*   ei = (const int*)d_in[1];
    const float* W1 = (const float*)d_in[2];
    const float* b1 = (const float*)d_in[3];
    const float* W2 = (const float*)d_in[4];
    const float* b2 = (const float*)d_in[5];
    float* z = (float*)d_out;

    const int4* src4 = (const int4*)ei;
    const int4* dst4 = (const int4*)(ei + N_EDGES);

    k_zero_deg  <<<(N_NODES + 255) / 256, 256>>>();
    k_count_deg <<<(N_EDGES / 8 + 255) / 256, 256>>>(dst4);
    k_bsum      <<<SCAN_NB, SCAN_BS>>>();
    k_fuse      <<<SCAN_NB + 1, SCAN_BS>>>(x, W1, b1, W2);
    k_bin       <<<(N_EDGES / 8 + 255) / 256, 256>>>(src4, dst4);

    k_agg<0>    <<<(N_NODES + 7) / 8, 256>>>(z, b2);
    k_agg<1>    <<<(N_NODES + 7) / 8, 256>>>(z, b2);
}